// round 3
// baseline (speedup 1.0000x reference)
#include <cuda_runtime.h>
#include <math.h>

#define BB 65536
#define D 128
#define NH 4
#define DH 32
#define DMLP 512
#define DMEM 64
#define NP 150
#define EQTOK 151
#define NOUT 150
#define NPAD 160
#define PADA 132
#define PADX 132

// ---------------- persistent scratch (static __device__; no runtime allocs) ----------------
__device__ float g_X3F[NP*D];      // x row3 (emb[EQ]+pos3+mem[p])
__device__ float g_Q3[NP*D];       // q of row3, pre-scaled by 1/sqrt(DH)
__device__ float g_V0[NP*D];
__device__ float g_V3[NP*D];
__device__ float g_VM[NP*D];       // mem[p] @ W_V
__device__ float g_S0[NP*NH];      // q3 . k0
__device__ float g_S3[NP*NH];      // q3 . k3
__device__ float g_SM[NP*NH];      // q3 . km
__device__ float g_K1T[NP*D];      // (emb[t]+pos1) @ W_K
__device__ float g_V1T[NP*D];
__device__ float g_K2T[NP*D];
__device__ float g_V2T[NP*D];
__device__ float g_T1[NP*NP*NH];   // q3[p] . K1T[a]  per head
__device__ float g_T2[NP*NP*NH];
__device__ float g_Wcat[(D+DMLP)*NPAD];  // [Wun ; W2@Wun] padded to 160 cols
__device__ float g_biasC[NPAD];          // b_un + b2@Wun
__device__ float g_Abuf[BB*D];           // per-example attention row3 (pre-W_O)
__device__ float g_X3buf[BB*D];          // x3 after attention residual
__device__ float g_Hbuf[(size_t)BB*DMLP];// relu MLP hidden

// ---------------- precompute per-p and per-token tables ----------------
__global__ void k_precompute(
    const float* __restrict__ emb, const float* __restrict__ pos,
    const float* __restrict__ W_mem, const float* __restrict__ b_mem,
    const float* __restrict__ W_sur, const float* __restrict__ b_sur,
    const float* __restrict__ W_m2r, const float* __restrict__ b_m2r,
    const float* __restrict__ W_Q, const float* __restrict__ W_K,
    const float* __restrict__ W_V)
{
    int p = blockIdx.x;
    int d = threadIdx.x; // 128 threads
    __shared__ float x0f[D], zz[DMEM], diffs[D], zu[DMEM], memv[D];
    __shared__ float x0full[D], x3full[D];
    __shared__ float sq[D], sk0[D], sk3[D], skm[D], e1v[D], e2v[D];

    x0f[d] = emb[p*D+d] + pos[d];
    __syncthreads();
    if (d < DMEM){
        float acc = b_mem[d];
        for (int e=0;e<D;e++) acc += x0f[e]*W_mem[e*DMEM+d];
        zz[d] = acc/(1.f+expf(-acc));        // silu
    }
    __syncthreads();
    {
        float pr = b_sur[d];
        for (int j=0;j<DMEM;j++) pr += zz[j]*W_sur[j*D+d];
        diffs[d] = x0f[d] - pr;
    }
    __syncthreads();
    if (d < DMEM){
        float acc = 0.f;                      // note: no bias
        for (int e=0;e<D;e++) acc += diffs[e]*W_mem[e*DMEM+d];
        zu[d] = zz[d] + acc/(1.f+expf(-acc));
    }
    __syncthreads();
    {
        float mm = b_m2r[d];
        for (int j=0;j<DMEM;j++) mm += zu[j]*W_m2r[j*D+d];
        memv[d]  = mm;
        x0full[d] = x0f[d] + mm;
        x3full[d] = emb[EQTOK*D+d] + pos[3*D+d] + mm;
        e1v[d] = emb[p*D+d] + pos[D+d];
        e2v[d] = emb[p*D+d] + pos[2*D+d];
    }
    __syncthreads();

    int h = d>>5, dh = d&31;
    const float* Wq = W_Q + h*D*DH + dh;
    const float* Wk = W_K + h*D*DH + dh;
    const float* Wv = W_V + h*D*DH + dh;
    float q=0,k0=0,k3=0,km=0,v0=0,v3=0,vm=0,k1=0,v1=0,k2=0,v2=0;
    for (int e=0;e<D;e++){
        float wq=Wq[e*DH], wk=Wk[e*DH], wv=Wv[e*DH];
        q  += x3full[e]*wq;
        k0 += x0full[e]*wk; k3 += x3full[e]*wk; km += memv[e]*wk;
        v0 += x0full[e]*wv; v3 += x3full[e]*wv; vm += memv[e]*wv;
        k1 += e1v[e]*wk;    v1 += e1v[e]*wv;
        k2 += e2v[e]*wk;    v2 += e2v[e]*wv;
    }
    q *= 0.17677669529663687f;  // 1/sqrt(32); folds attention scale into all scores
    g_Q3[p*D+d]=q;  g_X3F[p*D+d]=x3full[d];
    g_V0[p*D+d]=v0; g_V3[p*D+d]=v3; g_VM[p*D+d]=vm;
    g_K1T[p*D+d]=k1; g_V1T[p*D+d]=v1; g_K2T[p*D+d]=k2; g_V2T[p*D+d]=v2;
    sq[d]=q; sk0[d]=k0; sk3[d]=k3; skm[d]=km;
    __syncthreads();
    if (d < 3*NH){
        int hh = d & 3, which = d >> 2;
        const float* kk = (which==0) ? sk0 : (which==1 ? sk3 : skm);
        float acc=0.f;
        for (int t=0;t<DH;t++) acc += sq[hh*DH+t]*kk[hh*DH+t];
        float* dst = (which==0) ? g_S0 : (which==1 ? g_S3 : g_SM);
        dst[p*NH+hh] = acc;
    }
}

// ---------------- bilinear score tables T1/T2 ----------------
__global__ void k_ttab(){
    int p = blockIdx.x;
    __shared__ float q[D];
    int t = threadIdx.x;   // 128 threads
    q[t] = g_Q3[p*D+t];
    __syncthreads();
    for (int a=t; a<NP; a+=128){
        for (int h=0;h<NH;h++){
            float s1=0.f, s2=0.f;
            for (int k=0;k<DH;k++){
                float qv = q[h*DH+k];
                s1 += qv*g_K1T[a*D+h*DH+k];
                s2 += qv*g_K2T[a*D+h*DH+k];
            }
            g_T1[(p*NP+a)*NH+h] = s1;
            g_T2[(p*NP+a)*NH+h] = s2;
        }
    }
}

// ---------------- fold W2@Wun and bias ----------------
__global__ void k_wcat(const float* __restrict__ W_un, const float* __restrict__ b_un,
                       const float* __restrict__ W2,   const float* __restrict__ b2){
    int r = blockIdx.x;      // 0..639
    int n = threadIdx.x;     // 0..159
    float val = 0.f;
    if (n < NOUT){
        if (r < D) val = W_un[r*NOUT+n];
        else {
            int j = r - D;
            float acc = 0.f;
            for (int dd=0;dd<D;dd++) acc += W2[j*D+dd]*W_un[dd*NOUT+n];
            val = acc;
        }
    }
    g_Wcat[r*NPAD+n] = val;
    if (r == 0){
        float bc = 0.f;
        if (n < NOUT){
            bc = b_un[n];
            for (int dd=0;dd<D;dd++) bc += b2[dd]*W_un[dd*NOUT+n];
        }
        g_biasC[n] = bc;
    }
}

// ---------------- per-example attention (row 3 only), warp per example ----------------
__global__ void k_attn(const int* __restrict__ pv, const int* __restrict__ av,
                       const int* __restrict__ bv){
    int idx  = blockIdx.x*blockDim.x + threadIdx.x;
    int ex   = idx >> 5;
    int lane = idx & 31;
    int p = pv[ex], a = av[ex], b = bv[ex];
    int h = lane >> 3;                          // lane*4 dims are within one head
    float smv = g_SM[p*NH+h];
    float s0  = g_S0[p*NH+h];
    float s3  = g_S3[p*NH+h];
    float s1  = g_T1[(p*NP+a)*NH+h] + smv;
    float s2  = g_T2[(p*NP+b)*NH+h] + smv;
    float m  = fmaxf(fmaxf(s0,s1),fmaxf(s2,s3));
    float e0=expf(s0-m), e1=expf(s1-m), e2=expf(s2-m), e3=expf(s3-m);
    float inv = 1.f/(e0+e1+e2+e3);
    float w0=e0*inv, w1=e1*inv, w2=e2*inv, w3=e3*inv, w12=w1+w2;
    int d0 = lane*4;
    float4 V0 = *(const float4*)&g_V0 [p*D+d0];
    float4 V3 = *(const float4*)&g_V3 [p*D+d0];
    float4 VM = *(const float4*)&g_VM [p*D+d0];
    float4 Va = *(const float4*)&g_V1T[a*D+d0];
    float4 Vb = *(const float4*)&g_V2T[b*D+d0];
    float4 o;
    o.x = w0*V0.x + w3*V3.x + w12*VM.x + w1*Va.x + w2*Vb.x;
    o.y = w0*V0.y + w3*V3.y + w12*VM.y + w1*Va.y + w2*Vb.y;
    o.z = w0*V0.z + w3*V3.z + w12*VM.z + w1*Va.z + w2*Vb.z;
    o.w = w0*V0.w + w3*V3.w + w12*VM.w + w1*Va.w + w2*Vb.w;
    *(float4*)&g_Abuf[ex*D+d0] = o;
}

// ---------------- GEMM chain kernel 1: x3 = X3F[p] + A@W_O ; H = relu(x3@W1+b1) ----------------
__global__ void __launch_bounds__(256)
k_gemm1(const int* __restrict__ pv, const float* __restrict__ WO,
        const float* __restrict__ W1, const float* __restrict__ bias1){
    extern __shared__ float smem[];
    float* As = smem;             // [128][PADA]  (row, k)
    float* Ws = smem + D*PADA;    // [128][PADA]  (k, col)
    __shared__ int ps[D];
    int tid = threadIdx.x;
    int R0  = blockIdx.x * D;
    int tx = tid & 15, ty = tid >> 4;
    int r0 = ty*8, c0 = tx*8;

    for (int i=tid; i<D*32; i+=256){
        int row=i>>5, k4=(i&31)*4;
        *(float4*)&As[row*PADA+k4] = *(const float4*)&g_Abuf[(R0+row)*D+k4];
    }
    for (int i=tid; i<D*32; i+=256){
        int k=i>>5, c4=(i&31)*4;
        *(float4*)&Ws[k*PADA+c4] = *(const float4*)&WO[k*D+c4];  // W_O is already [(h*32+k)][128]
    }
    if (tid < D) ps[tid] = pv[R0+tid];
    __syncthreads();

    float acc[8][8];
    #pragma unroll
    for (int i=0;i<8;i++){
        #pragma unroll
        for (int j=0;j<8;j++) acc[i][j]=0.f;
    }
    for (int k=0;k<D;k++){
        float bvec[8];
        float4 b0 = *(float4*)&Ws[k*PADA+c0];
        float4 b1 = *(float4*)&Ws[k*PADA+c0+4];
        bvec[0]=b0.x;bvec[1]=b0.y;bvec[2]=b0.z;bvec[3]=b0.w;
        bvec[4]=b1.x;bvec[5]=b1.y;bvec[6]=b1.z;bvec[7]=b1.w;
        #pragma unroll
        for (int i=0;i<8;i++){
            float avv = As[(r0+i)*PADA+k];
            #pragma unroll
            for (int j=0;j<8;j++) acc[i][j] += avv*bvec[j];
        }
    }
    __syncthreads();

    float xv[8][8];
    #pragma unroll
    for (int i=0;i<8;i++){
        int pp = ps[r0+i];
        #pragma unroll
        for (int j=0;j<8;j++) xv[i][j] = acc[i][j] + g_X3F[pp*D+c0+j];
    }
    #pragma unroll
    for (int i=0;i<8;i++){
        #pragma unroll
        for (int j=0;j<8;j++) As[(r0+i)*PADA+c0+j] = xv[i][j];   // x3 in shared (row,k)
        *(float4*)&g_X3buf[(R0+r0+i)*D+c0]   = make_float4(xv[i][0],xv[i][1],xv[i][2],xv[i][3]);
        *(float4*)&g_X3buf[(R0+r0+i)*D+c0+4] = make_float4(xv[i][4],xv[i][5],xv[i][6],xv[i][7]);
    }
    __syncthreads();

    for (int ch=0; ch<4; ch++){
        for (int i=tid; i<D*32; i+=256){
            int k=i>>5, j4=(i&31)*4;
            *(float4*)&Ws[k*PADA+j4] = *(const float4*)&W1[k*DMLP + ch*D + j4];
        }
        __syncthreads();
        float acc2[8][8];
        #pragma unroll
        for (int i=0;i<8;i++){
            #pragma unroll
            for (int j=0;j<8;j++) acc2[i][j]=0.f;
        }
        for (int k=0;k<D;k++){
            float bvec[8];
            float4 b0 = *(float4*)&Ws[k*PADA+c0];
            float4 b1 = *(float4*)&Ws[k*PADA+c0+4];
            bvec[0]=b0.x;bvec[1]=b0.y;bvec[2]=b0.z;bvec[3]=b0.w;
            bvec[4]=b1.x;bvec[5]=b1.y;bvec[6]=b1.z;bvec[7]=b1.w;
            #pragma unroll
            for (int i=0;i<8;i++){
                float avv = As[(r0+i)*PADA+k];
                #pragma unroll
                for (int j=0;j<8;j++) acc2[i][j] += avv*bvec[j];
            }
        }
        #pragma unroll
        for (int i=0;i<8;i++){
            float4 o0, o1;
            o0.x = fmaxf(acc2[i][0]+bias1[ch*D+c0+0],0.f);
            o0.y = fmaxf(acc2[i][1]+bias1[ch*D+c0+1],0.f);
            o0.z = fmaxf(acc2[i][2]+bias1[ch*D+c0+2],0.f);
            o0.w = fmaxf(acc2[i][3]+bias1[ch*D+c0+3],0.f);
            o1.x = fmaxf(acc2[i][4]+bias1[ch*D+c0+4],0.f);
            o1.y = fmaxf(acc2[i][5]+bias1[ch*D+c0+5],0.f);
            o1.z = fmaxf(acc2[i][6]+bias1[ch*D+c0+6],0.f);
            o1.w = fmaxf(acc2[i][7]+bias1[ch*D+c0+7],0.f);
            size_t base = (size_t)(R0+r0+i)*DMLP + ch*D + c0;
            *(float4*)&g_Hbuf[base]   = o0;
            *(float4*)&g_Hbuf[base+4] = o1;
        }
        __syncthreads();
    }
}

// ---------------- GEMM chain kernel 2: logits = [X3 ; H] @ Wcat + biasC ----------------
__global__ void __launch_bounds__(256)
k_gemm2(float* __restrict__ out){
    extern __shared__ float smem[];
    float* Xs = smem;            // [128][PADX] (row, k)
    float* Ws = smem + D*PADX;   // [128][NPAD] (k, col)
    int tid = threadIdx.x;
    int R0  = blockIdx.x * D;
    int tx = tid & 15, ty = tid >> 4;
    int r0 = ty*8, c0 = tx*10;

    float acc[8][10];
    #pragma unroll
    for (int i=0;i<8;i++){
        #pragma unroll
        for (int j=0;j<10;j++) acc[i][j]=0.f;
    }

    for (int kc=0; kc<5; kc++){
        if (kc == 0){
            for (int i=tid; i<D*32; i+=256){
                int row=i>>5, k4=(i&31)*4;
                *(float4*)&Xs[row*PADX+k4] = *(const float4*)&g_X3buf[(R0+row)*D+k4];
            }
        } else {
            const float* src = &g_Hbuf[(size_t)R0*DMLP + (kc-1)*D];
            for (int i=tid; i<D*32; i+=256){
                int row=i>>5, k4=(i&31)*4;
                *(float4*)&Xs[row*PADX+k4] = *(const float4*)&src[(size_t)row*DMLP+k4];
            }
        }
        for (int i=tid; i<D*40; i+=256){
            int k=i/40, c4=(i%40)*4;
            *(float4*)&Ws[k*NPAD+c4] = *(const float4*)&g_Wcat[(kc*D+k)*NPAD+c4];
        }
        __syncthreads();
        for (int k=0;k<D;k++){
            float bv[10];
            #pragma unroll
            for (int j=0;j<10;j++) bv[j] = Ws[k*NPAD+c0+j];
            #pragma unroll
            for (int i=0;i<8;i++){
                float avv = Xs[(r0+i)*PADX+k];
                #pragma unroll
                for (int j=0;j<10;j++) acc[i][j] += avv*bv[j];
            }
        }
        __syncthreads();
    }
    #pragma unroll
    for (int i=0;i<8;i++){
        int row = R0 + r0 + i;
        #pragma unroll
        for (int j=0;j<10;j++){
            int c = c0 + j;
            if (c < NOUT) out[row*NOUT+c] = acc[i][j] + g_biasC[c];
        }
    }
}

// ---------------- launch ----------------
extern "C" void kernel_launch(void* const* d_in, const int* in_sizes, int n_in,
                              void* d_out, int out_size){
    const int*   pv    = (const int*)  d_in[0];
    const int*   av    = (const int*)  d_in[1];
    const int*   bvv   = (const int*)  d_in[2];
    const float* emb   = (const float*)d_in[3];
    const float* pos   = (const float*)d_in[4];
    const float* W_mem = (const float*)d_in[5];
    const float* b_mem = (const float*)d_in[6];
    const float* W_sur = (const float*)d_in[7];
    const float* b_sur = (const float*)d_in[8];
    const float* W_m2r = (const float*)d_in[9];
    const float* b_m2r = (const float*)d_in[10];
    const float* W_Q   = (const float*)d_in[11];
    const float* W_K   = (const float*)d_in[12];
    const float* W_V   = (const float*)d_in[13];
    const float* W_O   = (const float*)d_in[14];
    const float* W1    = (const float*)d_in[15];
    const float* bias1 = (const float*)d_in[16];
    const float* W2    = (const float*)d_in[17];
    const float* b2    = (const float*)d_in[18];
    const float* W_un  = (const float*)d_in[19];
    const float* b_un  = (const float*)d_in[20];
    float* out = (float*)d_out;

    k_precompute<<<NP,128>>>(emb,pos,W_mem,b_mem,W_sur,b_sur,W_m2r,b_m2r,W_Q,W_K,W_V);
    k_ttab<<<NP,128>>>();
    k_wcat<<<D+DMLP,NPAD>>>(W_un,b_un,W2,b2);
    k_attn<<<BB/8,256>>>(pv,av,bvv);

    int smB = D*PADA*2*(int)sizeof(float);                 // 135168 B
    cudaFuncSetAttribute(k_gemm1, cudaFuncAttributeMaxDynamicSharedMemorySize, smB);
    k_gemm1<<<BB/D,256,smB>>>(pv,W_O,W1,bias1);

    int smC = (D*PADX + D*NPAD)*(int)sizeof(float);        // 149504 B
    cudaFuncSetAttribute(k_gemm2, cudaFuncAttributeMaxDynamicSharedMemorySize, smC);
    k_gemm2<<<BB/D,256,smC>>>(out);
}

// round 4
// speedup vs baseline: 1.1854x; 1.1854x over previous
#include <cuda_runtime.h>
#include <math.h>

#define BB 65536
#define D 128
#define NH 4
#define DH 32
#define DMLP 512
#define DMEM 64
#define NP 150
#define EQTOK 151
#define NOUT 150
#define NPAD 160
#define PADA 132
#define PADX 132

// ---------------- packed fp32x2 helpers (sm_103a FFMA2) ----------------
__device__ __forceinline__ unsigned long long ffma2(unsigned long long a,
                                                    unsigned long long b,
                                                    unsigned long long c){
    unsigned long long d;
    asm("fma.rn.f32x2 %0, %1, %2, %3;" : "=l"(d) : "l"(a), "l"(b), "l"(c));
    return d;
}
__device__ __forceinline__ unsigned long long pack2(float lo, float hi){
    unsigned long long r;
    asm("mov.b64 %0, {%1, %2};" : "=l"(r) : "f"(lo), "f"(hi));
    return r;
}
__device__ __forceinline__ float2 unpack2(unsigned long long v){
    float2 f;
    asm("mov.b64 {%0, %1}, %2;" : "=f"(f.x), "=f"(f.y) : "l"(v));
    return f;
}

// ---------------- persistent scratch (static __device__; no runtime allocs) ----------------
__device__ float g_X3F[NP*D];      // x row3 (emb[EQ]+pos3+mem[p])
__device__ float g_Q3[NP*D];       // q of row3, pre-scaled by 1/sqrt(DH)
__device__ float g_V0[NP*D];
__device__ float g_V3[NP*D];
__device__ float g_VM[NP*D];       // mem[p] @ W_V
__device__ float g_S0[NP*NH];      // q3 . k0
__device__ float g_S3[NP*NH];      // q3 . k3
__device__ float g_SM[NP*NH];      // q3 . km
__device__ float g_K1T[NP*D];      // (emb[t]+pos1) @ W_K
__device__ float g_V1T[NP*D];
__device__ float g_K2T[NP*D];
__device__ float g_V2T[NP*D];
__device__ float g_T1[NP*NP*NH];   // q3[p] . K1T[a]  per head
__device__ float g_T2[NP*NP*NH];
__device__ float g_Wcat[(D+DMLP)*NPAD];  // [Wun ; W2@Wun] padded to 160 cols
__device__ float g_biasC[NPAD];          // b_un + b2@Wun
__device__ float g_Abuf[BB*D];           // per-example attention row3 (pre-W_O)
__device__ float g_X3buf[BB*D];          // x3 after attention residual
__device__ float g_Hbuf[(size_t)BB*DMLP];// relu MLP hidden

// ---------------- precompute per-p and per-token tables ----------------
__global__ void k_precompute(
    const float* __restrict__ emb, const float* __restrict__ pos,
    const float* __restrict__ W_mem, const float* __restrict__ b_mem,
    const float* __restrict__ W_sur, const float* __restrict__ b_sur,
    const float* __restrict__ W_m2r, const float* __restrict__ b_m2r,
    const float* __restrict__ W_Q, const float* __restrict__ W_K,
    const float* __restrict__ W_V)
{
    int p = blockIdx.x;
    int d = threadIdx.x; // 128 threads
    __shared__ float x0f[D], zz[DMEM], diffs[D], zu[DMEM], memv[D];
    __shared__ float x0full[D], x3full[D];
    __shared__ float sq[D], sk0[D], sk3[D], skm[D], e1v[D], e2v[D];

    x0f[d] = emb[p*D+d] + pos[d];
    __syncthreads();
    if (d < DMEM){
        float acc = b_mem[d];
        for (int e=0;e<D;e++) acc += x0f[e]*W_mem[e*DMEM+d];
        zz[d] = acc/(1.f+expf(-acc));        // silu
    }
    __syncthreads();
    {
        float pr = b_sur[d];
        for (int j=0;j<DMEM;j++) pr += zz[j]*W_sur[j*D+d];
        diffs[d] = x0f[d] - pr;
    }
    __syncthreads();
    if (d < DMEM){
        float acc = 0.f;                      // note: no bias
        for (int e=0;e<D;e++) acc += diffs[e]*W_mem[e*DMEM+d];
        zu[d] = zz[d] + acc/(1.f+expf(-acc));
    }
    __syncthreads();
    {
        float mm = b_m2r[d];
        for (int j=0;j<DMEM;j++) mm += zu[j]*W_m2r[j*D+d];
        memv[d]  = mm;
        x0full[d] = x0f[d] + mm;
        x3full[d] = emb[EQTOK*D+d] + pos[3*D+d] + mm;
        e1v[d] = emb[p*D+d] + pos[D+d];
        e2v[d] = emb[p*D+d] + pos[2*D+d];
    }
    __syncthreads();

    int h = d>>5, dh = d&31;
    const float* Wq = W_Q + h*D*DH + dh;
    const float* Wk = W_K + h*D*DH + dh;
    const float* Wv = W_V + h*D*DH + dh;
    float q=0,k0=0,k3=0,km=0,v0=0,v3=0,vm=0,k1=0,v1=0,k2=0,v2=0;
    for (int e=0;e<D;e++){
        float wq=Wq[e*DH], wk=Wk[e*DH], wv=Wv[e*DH];
        q  += x3full[e]*wq;
        k0 += x0full[e]*wk; k3 += x3full[e]*wk; km += memv[e]*wk;
        v0 += x0full[e]*wv; v3 += x3full[e]*wv; vm += memv[e]*wv;
        k1 += e1v[e]*wk;    v1 += e1v[e]*wv;
        k2 += e2v[e]*wk;    v2 += e2v[e]*wv;
    }
    q *= 0.17677669529663687f;  // 1/sqrt(32); folds attention scale into all scores
    g_Q3[p*D+d]=q;  g_X3F[p*D+d]=x3full[d];
    g_V0[p*D+d]=v0; g_V3[p*D+d]=v3; g_VM[p*D+d]=vm;
    g_K1T[p*D+d]=k1; g_V1T[p*D+d]=v1; g_K2T[p*D+d]=k2; g_V2T[p*D+d]=v2;
    sq[d]=q; sk0[d]=k0; sk3[d]=k3; skm[d]=km;
    __syncthreads();
    if (d < 3*NH){
        int hh = d & 3, which = d >> 2;
        const float* kk = (which==0) ? sk0 : (which==1 ? sk3 : skm);
        float acc=0.f;
        for (int t=0;t<DH;t++) acc += sq[hh*DH+t]*kk[hh*DH+t];
        float* dst = (which==0) ? g_S0 : (which==1 ? g_S3 : g_SM);
        dst[p*NH+hh] = acc;
    }
}

// ---------------- bilinear score tables T1/T2 ----------------
__global__ void k_ttab(){
    int p = blockIdx.x;
    __shared__ float q[D];
    int t = threadIdx.x;   // 128 threads
    q[t] = g_Q3[p*D+t];
    __syncthreads();
    for (int a=t; a<NP; a+=128){
        for (int h=0;h<NH;h++){
            float s1=0.f, s2=0.f;
            for (int k=0;k<DH;k++){
                float qv = q[h*DH+k];
                s1 += qv*g_K1T[a*D+h*DH+k];
                s2 += qv*g_K2T[a*D+h*DH+k];
            }
            g_T1[(p*NP+a)*NH+h] = s1;
            g_T2[(p*NP+a)*NH+h] = s2;
        }
    }
}

// ---------------- fold W2@Wun and bias ----------------
__global__ void k_wcat(const float* __restrict__ W_un, const float* __restrict__ b_un,
                       const float* __restrict__ W2,   const float* __restrict__ b2){
    int r = blockIdx.x;      // 0..639
    int n = threadIdx.x;     // 0..159
    float val = 0.f;
    if (n < NOUT){
        if (r < D) val = W_un[r*NOUT+n];
        else {
            int j = r - D;
            float acc = 0.f;
            for (int dd=0;dd<D;dd++) acc += W2[j*D+dd]*W_un[dd*NOUT+n];
            val = acc;
        }
    }
    g_Wcat[r*NPAD+n] = val;
    if (r == 0){
        float bc = 0.f;
        if (n < NOUT){
            bc = b_un[n];
            for (int dd=0;dd<D;dd++) bc += b2[dd]*W_un[dd*NOUT+n];
        }
        g_biasC[n] = bc;
    }
}

// ---------------- per-example attention (row 3 only), warp per example ----------------
__global__ void k_attn(const int* __restrict__ pv, const int* __restrict__ av,
                       const int* __restrict__ bv){
    int idx  = blockIdx.x*blockDim.x + threadIdx.x;
    int ex   = idx >> 5;
    int lane = idx & 31;
    int p = pv[ex], a = av[ex], b = bv[ex];
    int h = lane >> 3;                          // lane*4 dims are within one head
    float smv = g_SM[p*NH+h];
    float s0  = g_S0[p*NH+h];
    float s3  = g_S3[p*NH+h];
    float s1  = g_T1[(p*NP+a)*NH+h] + smv;
    float s2  = g_T2[(p*NP+b)*NH+h] + smv;
    float m  = fmaxf(fmaxf(s0,s1),fmaxf(s2,s3));
    float e0=expf(s0-m), e1=expf(s1-m), e2=expf(s2-m), e3=expf(s3-m);
    float inv = 1.f/(e0+e1+e2+e3);
    float w0=e0*inv, w1=e1*inv, w2=e2*inv, w3=e3*inv, w12=w1+w2;
    int d0 = lane*4;
    float4 V0 = *(const float4*)&g_V0 [p*D+d0];
    float4 V3 = *(const float4*)&g_V3 [p*D+d0];
    float4 VM = *(const float4*)&g_VM [p*D+d0];
    float4 Va = *(const float4*)&g_V1T[a*D+d0];
    float4 Vb = *(const float4*)&g_V2T[b*D+d0];
    float4 o;
    o.x = w0*V0.x + w3*V3.x + w12*VM.x + w1*Va.x + w2*Vb.x;
    o.y = w0*V0.y + w3*V3.y + w12*VM.y + w1*Va.y + w2*Vb.y;
    o.z = w0*V0.z + w3*V3.z + w12*VM.z + w1*Va.z + w2*Vb.z;
    o.w = w0*V0.w + w3*V3.w + w12*VM.w + w1*Va.w + w2*Vb.w;
    *(float4*)&g_Abuf[ex*D+d0] = o;
}

// ---------------- GEMM chain kernel 1: x3 = X3F[p] + A@W_O ; H = relu(x3@W1+b1) ----------------
__global__ void __launch_bounds__(256)
k_gemm1(const int* __restrict__ pv, const float* __restrict__ WO,
        const float* __restrict__ W1, const float* __restrict__ bias1){
    extern __shared__ float smem[];
    float* As = smem;             // [128][PADA]  (row, k)
    float* Ws = smem + D*PADA;    // [128][PADA]  (k, col)
    __shared__ int ps[D];
    int tid = threadIdx.x;
    int R0  = blockIdx.x * D;
    int tx = tid & 15, ty = tid >> 4;
    int r0 = ty*8, c0 = tx*8;

    for (int i=tid; i<D*32; i+=256){
        int row=i>>5, k4=(i&31)*4;
        *(float4*)&As[row*PADA+k4] = *(const float4*)&g_Abuf[(R0+row)*D+k4];
    }
    for (int i=tid; i<D*32; i+=256){
        int k=i>>5, c4=(i&31)*4;
        *(float4*)&Ws[k*PADA+c4] = *(const float4*)&WO[k*D+c4];  // W_O is already [(h*32+k)][128]
    }
    if (tid < D) ps[tid] = pv[R0+tid];
    __syncthreads();

    // ---- GEMM A@W_O with packed f32x2 (FFMA2) : acc pairs along j ----
    unsigned long long acc[8][4];
    #pragma unroll
    for (int i=0;i<8;i++){
        #pragma unroll
        for (int j=0;j<4;j++) acc[i][j]=0ull;
    }
    for (int k=0;k<D;k++){
        ulonglong2 b0 = *(ulonglong2*)&Ws[k*PADA+c0];
        ulonglong2 b1 = *(ulonglong2*)&Ws[k*PADA+c0+4];
        unsigned long long bv[4] = {b0.x, b0.y, b1.x, b1.y};
        #pragma unroll
        for (int i=0;i<8;i++){
            float avv = As[(r0+i)*PADA+k];
            unsigned long long aa = pack2(avv, avv);
            #pragma unroll
            for (int j=0;j<4;j++) acc[i][j] = ffma2(aa, bv[j], acc[i][j]);
        }
    }
    __syncthreads();

    float xv[8][8];
    #pragma unroll
    for (int i=0;i<8;i++){
        int pp = ps[r0+i];
        #pragma unroll
        for (int j=0;j<4;j++){
            float2 u = unpack2(acc[i][j]);
            xv[i][2*j]   = u.x + g_X3F[pp*D+c0+2*j];
            xv[i][2*j+1] = u.y + g_X3F[pp*D+c0+2*j+1];
        }
    }
    #pragma unroll
    for (int i=0;i<8;i++){
        #pragma unroll
        for (int j=0;j<8;j++) As[(r0+i)*PADA+c0+j] = xv[i][j];   // x3 in shared (row,k)
        *(float4*)&g_X3buf[(R0+r0+i)*D+c0]   = make_float4(xv[i][0],xv[i][1],xv[i][2],xv[i][3]);
        *(float4*)&g_X3buf[(R0+r0+i)*D+c0+4] = make_float4(xv[i][4],xv[i][5],xv[i][6],xv[i][7]);
    }
    __syncthreads();

    for (int ch=0; ch<4; ch++){
        for (int i=tid; i<D*32; i+=256){
            int k=i>>5, j4=(i&31)*4;
            *(float4*)&Ws[k*PADA+j4] = *(const float4*)&W1[k*DMLP + ch*D + j4];
        }
        __syncthreads();
        unsigned long long acc2[8][4];
        #pragma unroll
        for (int i=0;i<8;i++){
            #pragma unroll
            for (int j=0;j<4;j++) acc2[i][j]=0ull;
        }
        for (int k=0;k<D;k++){
            ulonglong2 b0 = *(ulonglong2*)&Ws[k*PADA+c0];
            ulonglong2 b1 = *(ulonglong2*)&Ws[k*PADA+c0+4];
            unsigned long long bv[4] = {b0.x, b0.y, b1.x, b1.y};
            #pragma unroll
            for (int i=0;i<8;i++){
                float avv = As[(r0+i)*PADA+k];
                unsigned long long aa = pack2(avv, avv);
                #pragma unroll
                for (int j=0;j<4;j++) acc2[i][j] = ffma2(aa, bv[j], acc2[i][j]);
            }
        }
        #pragma unroll
        for (int i=0;i<8;i++){
            float av[8];
            #pragma unroll
            for (int j=0;j<4;j++){
                float2 u = unpack2(acc2[i][j]);
                av[2*j]   = u.x;
                av[2*j+1] = u.y;
            }
            float4 o0, o1;
            o0.x = fmaxf(av[0]+bias1[ch*D+c0+0],0.f);
            o0.y = fmaxf(av[1]+bias1[ch*D+c0+1],0.f);
            o0.z = fmaxf(av[2]+bias1[ch*D+c0+2],0.f);
            o0.w = fmaxf(av[3]+bias1[ch*D+c0+3],0.f);
            o1.x = fmaxf(av[4]+bias1[ch*D+c0+4],0.f);
            o1.y = fmaxf(av[5]+bias1[ch*D+c0+5],0.f);
            o1.z = fmaxf(av[6]+bias1[ch*D+c0+6],0.f);
            o1.w = fmaxf(av[7]+bias1[ch*D+c0+7],0.f);
            size_t base = (size_t)(R0+r0+i)*DMLP + ch*D + c0;
            *(float4*)&g_Hbuf[base]   = o0;
            *(float4*)&g_Hbuf[base+4] = o1;
        }
        __syncthreads();
    }
}

// ---------------- GEMM chain kernel 2: logits = [X3 ; H] @ Wcat + biasC ----------------
__global__ void __launch_bounds__(256)
k_gemm2(float* __restrict__ out){
    extern __shared__ float smem[];
    float* Xs = smem;            // [128][PADX] (row, k)
    float* Ws = smem + D*PADX;   // [128][NPAD] (k, col)
    int tid = threadIdx.x;
    int R0  = blockIdx.x * D;
    int tx = tid & 15, ty = tid >> 4;
    int r0 = ty*8, c0 = tx*10;   // c0 even -> 8B aligned for f32x2

    unsigned long long acc[8][5];
    #pragma unroll
    for (int i=0;i<8;i++){
        #pragma unroll
        for (int j=0;j<5;j++) acc[i][j]=0ull;
    }

    for (int kc=0; kc<5; kc++){
        if (kc == 0){
            for (int i=tid; i<D*32; i+=256){
                int row=i>>5, k4=(i&31)*4;
                *(float4*)&Xs[row*PADX+k4] = *(const float4*)&g_X3buf[(R0+row)*D+k4];
            }
        } else {
            const float* src = &g_Hbuf[(size_t)R0*DMLP + (kc-1)*D];
            for (int i=tid; i<D*32; i+=256){
                int row=i>>5, k4=(i&31)*4;
                *(float4*)&Xs[row*PADX+k4] = *(const float4*)&src[(size_t)row*DMLP+k4];
            }
        }
        for (int i=tid; i<D*40; i+=256){
            int k=i/40, c4=(i%40)*4;
            *(float4*)&Ws[k*NPAD+c4] = *(const float4*)&g_Wcat[(kc*D+k)*NPAD+c4];
        }
        __syncthreads();
        for (int k=0;k<D;k++){
            unsigned long long bv[5];
            #pragma unroll
            for (int j=0;j<5;j++) bv[j] = *(unsigned long long*)&Ws[k*NPAD+c0+2*j];
            #pragma unroll
            for (int i=0;i<8;i++){
                float avv = Xs[(r0+i)*PADX+k];
                unsigned long long aa = pack2(avv, avv);
                #pragma unroll
                for (int j=0;j<5;j++) acc[i][j] = ffma2(aa, bv[j], acc[i][j]);
            }
        }
        __syncthreads();
    }
    #pragma unroll
    for (int i=0;i<8;i++){
        int row = R0 + r0 + i;
        float av[10];
        #pragma unroll
        for (int j=0;j<5;j++){
            float2 u = unpack2(acc[i][j]);
            av[2*j]   = u.x;
            av[2*j+1] = u.y;
        }
        #pragma unroll
        for (int j=0;j<10;j++){
            int c = c0 + j;
            if (c < NOUT) out[row*NOUT+c] = av[j] + g_biasC[c];
        }
    }
}

// ---------------- launch ----------------
extern "C" void kernel_launch(void* const* d_in, const int* in_sizes, int n_in,
                              void* d_out, int out_size){
    const int*   pv    = (const int*)  d_in[0];
    const int*   av    = (const int*)  d_in[1];
    const int*   bvv   = (const int*)  d_in[2];
    const float* emb   = (const float*)d_in[3];
    const float* pos   = (const float*)d_in[4];
    const float* W_mem = (const float*)d_in[5];
    const float* b_mem = (const float*)d_in[6];
    const float* W_sur = (const float*)d_in[7];
    const float* b_sur = (const float*)d_in[8];
    const float* W_m2r = (const float*)d_in[9];
    const float* b_m2r = (const float*)d_in[10];
    const float* W_Q   = (const float*)d_in[11];
    const float* W_K   = (const float*)d_in[12];
    const float* W_V   = (const float*)d_in[13];
    const float* W_O   = (const float*)d_in[14];
    const float* W1    = (const float*)d_in[15];
    const float* bias1 = (const float*)d_in[16];
    const float* W2    = (const float*)d_in[17];
    const float* b2    = (const float*)d_in[18];
    const float* W_un  = (const float*)d_in[19];
    const float* b_un  = (const float*)d_in[20];
    float* out = (float*)d_out;

    k_precompute<<<NP,128>>>(emb,pos,W_mem,b_mem,W_sur,b_sur,W_m2r,b_m2r,W_Q,W_K,W_V);
    k_ttab<<<NP,128>>>();
    k_wcat<<<D+DMLP,NPAD>>>(W_un,b_un,W2,b2);
    k_attn<<<BB/8,256>>>(pv,av,bvv);

    int smB = D*PADA*2*(int)sizeof(float);                 // 135168 B
    cudaFuncSetAttribute(k_gemm1, cudaFuncAttributeMaxDynamicSharedMemorySize, smB);
    k_gemm1<<<BB/D,256,smB>>>(pv,W_O,W1,bias1);

    int smC = (D*PADX + D*NPAD)*(int)sizeof(float);        // 149504 B
    cudaFuncSetAttribute(k_gemm2, cudaFuncAttributeMaxDynamicSharedMemorySize, smC);
    k_gemm2<<<BB/D,256,smC>>>(out);
}

// round 6
// speedup vs baseline: 1.5192x; 1.2816x over previous
#include <cuda_runtime.h>
#include <cuda_bf16.h>
#include <math.h>
#include <stdint.h>

#define BB 65536
#define D 128
#define NH 4
#define DH 32
#define DMLP 512
#define DMEM 64
#define NP 150
#define EQTOK 151
#define NOUT 150
#define NPAD 160
#define PADA 132

// ---------------- packed fp32x2 helpers (sm_103a FFMA2) ----------------
__device__ __forceinline__ unsigned long long ffma2(unsigned long long a,
                                                    unsigned long long b,
                                                    unsigned long long c){
    unsigned long long d;
    asm("fma.rn.f32x2 %0, %1, %2, %3;" : "=l"(d) : "l"(a), "l"(b), "l"(c));
    return d;
}
__device__ __forceinline__ unsigned long long pack2(float lo, float hi){
    unsigned long long r;
    asm("mov.b64 %0, {%1, %2};" : "=l"(r) : "f"(lo), "f"(hi));
    return r;
}
__device__ __forceinline__ float2 unpack2(unsigned long long v){
    float2 f;
    asm("mov.b64 {%0, %1}, %2;" : "=f"(f.x), "=f"(f.y) : "l"(v));
    return f;
}

// ---------------- warp-level bf16 tensor-core mma (HMMA, arch-generic) ----------------
__device__ __forceinline__ void mma16816(float* c, const uint32_t* a, const uint32_t* b){
    asm volatile(
        "mma.sync.aligned.m16n8k16.row.col.f32.bf16.bf16.f32 "
        "{%0,%1,%2,%3}, {%4,%5,%6,%7}, {%8,%9}, {%0,%1,%2,%3};"
        : "+f"(c[0]), "+f"(c[1]), "+f"(c[2]), "+f"(c[3])
        : "r"(a[0]), "r"(a[1]), "r"(a[2]), "r"(a[3]), "r"(b[0]), "r"(b[1]));
}

// ---------------- persistent scratch ----------------
__device__ float g_X3F[NP*D];
__device__ float g_Q3[NP*D];
__device__ float g_V0[NP*D];
__device__ float g_V3[NP*D];
__device__ float g_VM[NP*D];
__device__ float g_S0[NP*NH];
__device__ float g_S3[NP*NH];
__device__ float g_SM[NP*NH];
__device__ float g_K1T[NP*D];
__device__ float g_V1T[NP*D];
__device__ float g_K2T[NP*D];
__device__ float g_V2T[NP*D];
__device__ float g_T1[NP*NP*NH];
__device__ float g_T2[NP*NP*NH];
__device__ float g_biasC[NPAD];
__device__ float g_Abuf[BB*D];
// bf16 hi/lo A-operand images: [512 blocks][5 slabs][128 rows x 128 k, chunk-XOR swizzled = 32KB]
__device__ uint4 g_AimgHi[(size_t)512*5*2048];
__device__ uint4 g_AimgLo[(size_t)512*5*2048];
// bf16 hi/lo B-operand (WcatT) images: [5 slabs][160 rows x 128 k = 40KB]
__device__ uint4 g_WimgHi[5*2560];
__device__ uint4 g_WimgLo[5*2560];

// image addressing: row-major 256B rows of bf16[128], 16B chunks XOR-swizzled by (row&7)
__device__ __forceinline__ unsigned img_off_elem(int r, int k){
    return (unsigned)r*256u + ((((unsigned)k>>3)^((unsigned)r&7u))*16u) + ((unsigned)k&7u)*2u;
}
__device__ __forceinline__ unsigned img_off_chunk(int r, int k0){  // k0 multiple of 8
    return (unsigned)r*256u + ((((unsigned)k0>>3)^((unsigned)r&7u))*16u);
}

// split f32 -> bf16 hi + bf16 lo, write 8 consecutive cols (one 16B chunk)
__device__ __forceinline__ void writeAimg(char* hiB, char* loB, int r, int k0, const float* v){
    union { unsigned short s[8]; uint4 q; } H, L;
    #pragma unroll
    for (int j=0;j<8;j++){
        float x = v[j];
        __nv_bfloat16 h = __float2bfloat16(x);
        float res = x - __bfloat162float(h);
        __nv_bfloat16 l = __float2bfloat16(res);
        H.s[j] = *(unsigned short*)&h;
        L.s[j] = *(unsigned short*)&l;
    }
    unsigned off = img_off_chunk(r, k0);
    *(uint4*)(hiB + off) = H.q;
    *(uint4*)(loB + off) = L.q;
}

// ---------------- precompute per-p and per-token tables ----------------
__global__ void k_precompute(
    const float* __restrict__ emb, const float* __restrict__ pos,
    const float* __restrict__ W_mem, const float* __restrict__ b_mem,
    const float* __restrict__ W_sur, const float* __restrict__ b_sur,
    const float* __restrict__ W_m2r, const float* __restrict__ b_m2r,
    const float* __restrict__ W_Q, const float* __restrict__ W_K,
    const float* __restrict__ W_V)
{
    int p = blockIdx.x;
    int d = threadIdx.x; // 128 threads
    __shared__ float x0f[D], zz[DMEM], diffs[D], zu[DMEM], memv[D];
    __shared__ float x0full[D], x3full[D];
    __shared__ float sq[D], sk0[D], sk3[D], skm[D], e1v[D], e2v[D];

    x0f[d] = emb[p*D+d] + pos[d];
    __syncthreads();
    if (d < DMEM){
        float acc = b_mem[d];
        for (int e=0;e<D;e++) acc += x0f[e]*W_mem[e*DMEM+d];
        zz[d] = acc/(1.f+expf(-acc));        // silu
    }
    __syncthreads();
    {
        float pr = b_sur[d];
        for (int j=0;j<DMEM;j++) pr += zz[j]*W_sur[j*D+d];
        diffs[d] = x0f[d] - pr;
    }
    __syncthreads();
    if (d < DMEM){
        float acc = 0.f;
        for (int e=0;e<D;e++) acc += diffs[e]*W_mem[e*DMEM+d];
        zu[d] = zz[d] + acc/(1.f+expf(-acc));
    }
    __syncthreads();
    {
        float mm = b_m2r[d];
        for (int j=0;j<DMEM;j++) mm += zu[j]*W_m2r[j*D+d];
        memv[d]  = mm;
        x0full[d] = x0f[d] + mm;
        x3full[d] = emb[EQTOK*D+d] + pos[3*D+d] + mm;
        e1v[d] = emb[p*D+d] + pos[D+d];
        e2v[d] = emb[p*D+d] + pos[2*D+d];
    }
    __syncthreads();

    int h = d>>5;
    const float* Wq = W_Q + h*D*DH + (d&31);
    const float* Wk = W_K + h*D*DH + (d&31);
    const float* Wv = W_V + h*D*DH + (d&31);
    float q=0,k0=0,k3=0,km=0,v0=0,v3=0,vm=0,k1=0,v1=0,k2=0,v2=0;
    for (int e=0;e<D;e++){
        float wq=Wq[e*DH], wk=Wk[e*DH], wv=Wv[e*DH];
        q  += x3full[e]*wq;
        k0 += x0full[e]*wk; k3 += x3full[e]*wk; km += memv[e]*wk;
        v0 += x0full[e]*wv; v3 += x3full[e]*wv; vm += memv[e]*wv;
        k1 += e1v[e]*wk;    v1 += e1v[e]*wv;
        k2 += e2v[e]*wk;    v2 += e2v[e]*wv;
    }
    q *= 0.17677669529663687f;  // 1/sqrt(32)
    g_Q3[p*D+d]=q;  g_X3F[p*D+d]=x3full[d];
    g_V0[p*D+d]=v0; g_V3[p*D+d]=v3; g_VM[p*D+d]=vm;
    g_K1T[p*D+d]=k1; g_V1T[p*D+d]=v1; g_K2T[p*D+d]=k2; g_V2T[p*D+d]=v2;
    sq[d]=q; sk0[d]=k0; sk3[d]=k3; skm[d]=km;
    __syncthreads();
    if (d < 3*NH){
        int hh = d & 3, which = d >> 2;
        const float* kk = (which==0) ? sk0 : (which==1 ? sk3 : skm);
        float acc=0.f;
        for (int t=0;t<DH;t++) acc += sq[hh*DH+t]*kk[hh*DH+t];
        float* dst = (which==0) ? g_S0 : (which==1 ? g_S3 : g_SM);
        dst[p*NH+hh] = acc;
    }
}

// ---------------- bilinear score tables T1/T2 ----------------
__global__ void k_ttab(){
    int p = blockIdx.x;
    __shared__ float q[D];
    int t = threadIdx.x;
    q[t] = g_Q3[p*D+t];
    __syncthreads();
    for (int a=t; a<NP; a+=128){
        for (int h=0;h<NH;h++){
            float s1=0.f, s2=0.f;
            for (int k=0;k<DH;k++){
                float qv = q[h*DH+k];
                s1 += qv*g_K1T[a*D+h*DH+k];
                s2 += qv*g_K2T[a*D+h*DH+k];
            }
            g_T1[(p*NP+a)*NH+h] = s1;
            g_T2[(p*NP+a)*NH+h] = s2;
        }
    }
}

// ---------------- fold W2@Wun, bias, and build WcatT bf16 hi/lo images ----------------
__global__ void k_wcat(const float* __restrict__ W_un, const float* __restrict__ b_un,
                       const float* __restrict__ W2,   const float* __restrict__ b2){
    int r = blockIdx.x;      // 0..639  (K dim of Wcat)
    int n = threadIdx.x;     // 0..159  (output col)
    float val = 0.f;
    if (n < NOUT){
        if (r < D) val = W_un[r*NOUT+n];
        else {
            int j = r - D;
            float acc = 0.f;
            for (int dd=0;dd<D;dd++) acc += W2[j*D+dd]*W_un[dd*NOUT+n];
            val = acc;
        }
    }
    int slab = r >> 7, kk = r & 127;
    __nv_bfloat16 h = __float2bfloat16(val);
    float res = val - __bfloat162float(h);
    __nv_bfloat16 l = __float2bfloat16(res);
    unsigned off = img_off_elem(n, kk);
    *(unsigned short*)((char*)g_WimgHi + (size_t)slab*40960 + off) = *(unsigned short*)&h;
    *(unsigned short*)((char*)g_WimgLo + (size_t)slab*40960 + off) = *(unsigned short*)&l;
    if (r == 0){
        float bc = 0.f;
        if (n < NOUT){
            bc = b_un[n];
            for (int dd=0;dd<D;dd++) bc += b2[dd]*W_un[dd*NOUT+n];
        }
        g_biasC[n] = bc;
    }
}

// ---------------- per-example attention (row 3 only) ----------------
__global__ void k_attn(const int* __restrict__ pv, const int* __restrict__ av,
                       const int* __restrict__ bv){
    int idx  = blockIdx.x*blockDim.x + threadIdx.x;
    int ex   = idx >> 5;
    int lane = idx & 31;
    int p = pv[ex], a = av[ex], b = bv[ex];
    int h = lane >> 3;
    float smv = g_SM[p*NH+h];
    float s0  = g_S0[p*NH+h];
    float s3  = g_S3[p*NH+h];
    float s1  = g_T1[(p*NP+a)*NH+h] + smv;
    float s2  = g_T2[(p*NP+b)*NH+h] + smv;
    float m  = fmaxf(fmaxf(s0,s1),fmaxf(s2,s3));
    float e0=expf(s0-m), e1=expf(s1-m), e2=expf(s2-m), e3=expf(s3-m);
    float inv = 1.f/(e0+e1+e2+e3);
    float w0=e0*inv, w1=e1*inv, w2=e2*inv, w3=e3*inv, w12=w1+w2;
    int d0 = lane*4;
    float4 V0 = *(const float4*)&g_V0 [p*D+d0];
    float4 V3 = *(const float4*)&g_V3 [p*D+d0];
    float4 VM = *(const float4*)&g_VM [p*D+d0];
    float4 Va = *(const float4*)&g_V1T[a*D+d0];
    float4 Vb = *(const float4*)&g_V2T[b*D+d0];
    float4 o;
    o.x = w0*V0.x + w3*V3.x + w12*VM.x + w1*Va.x + w2*Vb.x;
    o.y = w0*V0.y + w3*V3.y + w12*VM.y + w1*Va.y + w2*Vb.y;
    o.z = w0*V0.z + w3*V3.z + w12*VM.z + w1*Va.z + w2*Vb.z;
    o.w = w0*V0.w + w3*V3.w + w12*VM.w + w1*Va.w + w2*Vb.w;
    *(float4*)&g_Abuf[ex*D+d0] = o;
}

// ---------------- k_gemm1: x3 = X3F[p] + A@W_O ; H = relu(x3@W1+b1) (FFMA2)
// Epilogues write bf16 hi/lo swizzled images for the tensor-core gemm2.
__global__ void __launch_bounds__(256)
k_gemm1(const int* __restrict__ pv, const float* __restrict__ WO,
        const float* __restrict__ W1, const float* __restrict__ bias1){
    extern __shared__ float smem[];
    float* As = smem;             // [128][PADA]  (row, k)
    float* Ws = smem + D*PADA;    // [128][PADA]  (k, col)
    __shared__ int ps[D];
    int tid = threadIdx.x;
    int blk = blockIdx.x;
    int R0  = blk * D;
    int tx = tid & 15, ty = tid >> 4;
    int r0 = ty*8, c0 = tx*8;

    char* imgHi0 = (char*)g_AimgHi + (size_t)(blk*5)*32768;
    char* imgLo0 = (char*)g_AimgLo + (size_t)(blk*5)*32768;

    for (int i=tid; i<D*32; i+=256){
        int row=i>>5, k4=(i&31)*4;
        *(float4*)&As[row*PADA+k4] = *(const float4*)&g_Abuf[(R0+row)*D+k4];
    }
    for (int i=tid; i<D*32; i+=256){
        int k=i>>5, c4=(i&31)*4;
        *(float4*)&Ws[k*PADA+c4] = *(const float4*)&WO[k*D+c4];
    }
    if (tid < D) ps[tid] = pv[R0+tid];
    __syncthreads();

    unsigned long long acc[8][4];
    #pragma unroll
    for (int i=0;i<8;i++){
        #pragma unroll
        for (int j=0;j<4;j++) acc[i][j]=0ull;
    }
    for (int k=0;k<D;k++){
        ulonglong2 b0 = *(ulonglong2*)&Ws[k*PADA+c0];
        ulonglong2 b1 = *(ulonglong2*)&Ws[k*PADA+c0+4];
        unsigned long long bv[4] = {b0.x, b0.y, b1.x, b1.y};
        #pragma unroll
        for (int i=0;i<8;i++){
            float avv = As[(r0+i)*PADA+k];
            unsigned long long aa = pack2(avv, avv);
            #pragma unroll
            for (int j=0;j<4;j++) acc[i][j] = ffma2(aa, bv[j], acc[i][j]);
        }
    }
    __syncthreads();

    float xv[8][8];
    #pragma unroll
    for (int i=0;i<8;i++){
        int pp = ps[r0+i];
        #pragma unroll
        for (int j=0;j<4;j++){
            float2 u = unpack2(acc[i][j]);
            xv[i][2*j]   = u.x + g_X3F[pp*D+c0+2*j];
            xv[i][2*j+1] = u.y + g_X3F[pp*D+c0+2*j+1];
        }
    }
    #pragma unroll
    for (int i=0;i<8;i++){
        #pragma unroll
        for (int j=0;j<8;j++) As[(r0+i)*PADA+c0+j] = xv[i][j];   // x3 in shared
        writeAimg(imgHi0, imgLo0, r0+i, c0, xv[i]);              // slab 0 image (X3)
    }
    __syncthreads();

    for (int ch=0; ch<4; ch++){
        for (int i=tid; i<D*32; i+=256){
            int k=i>>5, j4=(i&31)*4;
            *(float4*)&Ws[k*PADA+j4] = *(const float4*)&W1[k*DMLP + ch*D + j4];
        }
        __syncthreads();
        unsigned long long acc2[8][4];
        #pragma unroll
        for (int i=0;i<8;i++){
            #pragma unroll
            for (int j=0;j<4;j++) acc2[i][j]=0ull;
        }
        for (int k=0;k<D;k++){
            ulonglong2 b0 = *(ulonglong2*)&Ws[k*PADA+c0];
            ulonglong2 b1 = *(ulonglong2*)&Ws[k*PADA+c0+4];
            unsigned long long bv[4] = {b0.x, b0.y, b1.x, b1.y};
            #pragma unroll
            for (int i=0;i<8;i++){
                float avv = As[(r0+i)*PADA+k];
                unsigned long long aa = pack2(avv, avv);
                #pragma unroll
                for (int j=0;j<4;j++) acc2[i][j] = ffma2(aa, bv[j], acc2[i][j]);
            }
        }
        char* imgHi = imgHi0 + (size_t)(ch+1)*32768;
        char* imgLo = imgLo0 + (size_t)(ch+1)*32768;
        #pragma unroll
        for (int i=0;i<8;i++){
            float av[8];
            #pragma unroll
            for (int j=0;j<4;j++){
                float2 u = unpack2(acc2[i][j]);
                av[2*j]   = fmaxf(u.x + bias1[ch*D+c0+2*j],   0.f);
                av[2*j+1] = fmaxf(u.y + bias1[ch*D+c0+2*j+1], 0.f);
            }
            writeAimg(imgHi, imgLo, r0+i, c0, av);               // slab ch+1 image (H)
        }
        __syncthreads();
    }
}

// ---------------- k_gemm2m: logits = [X3;H] @ Wcat + biasC  (mma.sync bf16 split) ----------------
#define OFF_AHI 0
#define OFF_ALO 32768
#define OFF_BHI 65536
#define OFF_BLO 106496
#define G2_SMEM 147456

__global__ void __launch_bounds__(256)
k_gemm2m(float* __restrict__ out){
    extern __shared__ char sm2[];
    int tid = threadIdx.x, wid = tid>>5, lane = tid&31;
    int blk = blockIdx.x;
    int R0  = blk * 128;
    int wm = wid & 3, wn = wid >> 2;          // 4 warps on M, 2 on N
    int rowbase = wm*32, colbase = wn*80;
    int lr = lane >> 2, lq = lane & 3;

    const uint4* aHiG = g_AimgHi + (size_t)blk*5*2048;
    const uint4* aLoG = g_AimgLo + (size_t)blk*5*2048;

    float acc[2][10][4];
    #pragma unroll
    for (int mt=0;mt<2;mt++){
        #pragma unroll
        for (int nt=0;nt<10;nt++){
            #pragma unroll
            for (int q=0;q<4;q++) acc[mt][nt][q]=0.f;
        }
    }

    for (int slab = 0; slab < 5; slab++){
        __syncthreads();   // previous slab fully consumed
        {
            uint4* dAh = (uint4*)(sm2 + OFF_AHI);
            uint4* dAl = (uint4*)(sm2 + OFF_ALO);
            const uint4* sAh = aHiG + slab*2048;
            const uint4* sAl = aLoG + slab*2048;
            for (int i = tid; i < 2048; i += 256){ dAh[i] = sAh[i]; dAl[i] = sAl[i]; }
            uint4* dBh = (uint4*)(sm2 + OFF_BHI);
            uint4* dBl = (uint4*)(sm2 + OFF_BLO);
            const uint4* sBh = g_WimgHi + slab*2560;
            const uint4* sBl = g_WimgLo + slab*2560;
            for (int i = tid; i < 2560; i += 256){ dBh[i] = sBh[i]; dBl[i] = sBl[i]; }
        }
        __syncthreads();

        #pragma unroll
        for (int ps = 0; ps < 3; ps++){
            const char* Aimg = sm2 + (ps==1 ? OFF_ALO : OFF_AHI);
            const char* Bimg = sm2 + (ps==2 ? OFF_BLO : OFF_BHI);
            #pragma unroll
            for (int ks = 0; ks < 8; ks++){
                int kb = ks*16;
                unsigned ch0 = (unsigned)(kb>>3), ch1 = ch0+1;
                uint32_t afr[2][4];
                #pragma unroll
                for (int mt=0;mt<2;mt++){
                    int r = rowbase + mt*16 + lr;
                    unsigned base = (unsigned)r*256u + (unsigned)lq*4u;
                    unsigned o0 = base + ((ch0^((unsigned)r&7u))*16u);
                    unsigned o1 = base + ((ch1^((unsigned)r&7u))*16u);
                    afr[mt][0] = *(const uint32_t*)(Aimg + o0);
                    afr[mt][1] = *(const uint32_t*)(Aimg + o0 + 2048);
                    afr[mt][2] = *(const uint32_t*)(Aimg + o1);
                    afr[mt][3] = *(const uint32_t*)(Aimg + o1 + 2048);
                }
                uint32_t bfr[10][2];
                #pragma unroll
                for (int nt=0;nt<10;nt++){
                    int n = colbase + nt*8 + lr;
                    unsigned base = (unsigned)n*256u + (unsigned)lq*4u;
                    bfr[nt][0] = *(const uint32_t*)(Bimg + base + ((ch0^((unsigned)n&7u))*16u));
                    bfr[nt][1] = *(const uint32_t*)(Bimg + base + ((ch1^((unsigned)n&7u))*16u));
                }
                #pragma unroll
                for (int mt=0;mt<2;mt++){
                    #pragma unroll
                    for (int nt=0;nt<10;nt++) mma16816(acc[mt][nt], afr[mt], bfr[nt]);
                }
            }
        }
    }

    // epilogue: c0,c1 at (row, col..col+1); c2,c3 at (row+8, col..col+1)
    #pragma unroll
    for (int mt=0;mt<2;mt++){
        int row = R0 + rowbase + mt*16 + lr;
        #pragma unroll
        for (int nt=0;nt<10;nt++){
            int col = colbase + nt*8 + lq*2;
            if (col < NOUT){
                out[row*NOUT+col]       = acc[mt][nt][0] + g_biasC[col];
                out[(row+8)*NOUT+col]   = acc[mt][nt][2] + g_biasC[col];
            }
            if (col+1 < NOUT){
                out[row*NOUT+col+1]     = acc[mt][nt][1] + g_biasC[col+1];
                out[(row+8)*NOUT+col+1] = acc[mt][nt][3] + g_biasC[col+1];
            }
        }
    }
}

// ---------------- launch ----------------
extern "C" void kernel_launch(void* const* d_in, const int* in_sizes, int n_in,
                              void* d_out, int out_size){
    const int*   pv    = (const int*)  d_in[0];
    const int*   av    = (const int*)  d_in[1];
    const int*   bvv   = (const int*)  d_in[2];
    const float* emb   = (const float*)d_in[3];
    const float* pos   = (const float*)d_in[4];
    const float* W_mem = (const float*)d_in[5];
    const float* b_mem = (const float*)d_in[6];
    const float* W_sur = (const float*)d_in[7];
    const float* b_sur = (const float*)d_in[8];
    const float* W_m2r = (const float*)d_in[9];
    const float* b_m2r = (const float*)d_in[10];
    const float* W_Q   = (const float*)d_in[11];
    const float* W_K   = (const float*)d_in[12];
    const float* W_V   = (const float*)d_in[13];
    const float* W_O   = (const float*)d_in[14];
    const float* W1    = (const float*)d_in[15];
    const float* bias1 = (const float*)d_in[16];
    const float* W2    = (const float*)d_in[17];
    const float* b2    = (const float*)d_in[18];
    const float* W_un  = (const float*)d_in[19];
    const float* b_un  = (const float*)d_in[20];
    float* out = (float*)d_out;

    k_precompute<<<NP,128>>>(emb,pos,W_mem,b_mem,W_sur,b_sur,W_m2r,b_m2r,W_Q,W_K,W_V);
    k_ttab<<<NP,128>>>();
    k_wcat<<<D+DMLP,NPAD>>>(W_un,b_un,W2,b2);
    k_attn<<<BB/8,256>>>(pv,av,bvv);

    int smB = D*PADA*2*(int)sizeof(float);
    cudaFuncSetAttribute(k_gemm1, cudaFuncAttributeMaxDynamicSharedMemorySize, smB);
    k_gemm1<<<BB/D,256,smB>>>(pv,W_O,W1,bias1);

    cudaFuncSetAttribute(k_gemm2m, cudaFuncAttributeMaxDynamicSharedMemorySize, G2_SMEM);
    k_gemm2m<<<BB/D,256,G2_SMEM>>>(out);
}

// round 7
// speedup vs baseline: 2.5320x; 1.6667x over previous
#include <cuda_runtime.h>
#include <cuda_bf16.h>
#include <math.h>
#include <stdint.h>

#define BB 65536
#define D 128
#define NH 4
#define DH 32
#define DMLP 512
#define DMEM 64
#define NP 150
#define EQTOK 151
#define NOUT 150
#define NPAD 160

// ---------------- warp-level bf16 tensor-core mma ----------------
__device__ __forceinline__ void mma16816(float* c, const uint32_t* a, const uint32_t* b){
    asm volatile(
        "mma.sync.aligned.m16n8k16.row.col.f32.bf16.bf16.f32 "
        "{%0,%1,%2,%3}, {%4,%5,%6,%7}, {%8,%9}, {%0,%1,%2,%3};"
        : "+f"(c[0]), "+f"(c[1]), "+f"(c[2]), "+f"(c[3])
        : "r"(a[0]), "r"(a[1]), "r"(a[2]), "r"(a[3]), "r"(b[0]), "r"(b[1]));
}

// ---------------- persistent scratch ----------------
__device__ float g_X3F[NP*D];
__device__ float g_Q3[NP*D];
__device__ float g_V0[NP*D];
__device__ float g_V3[NP*D];
__device__ float g_VM[NP*D];
__device__ float g_S0[NP*NH];
__device__ float g_S3[NP*NH];
__device__ float g_SM[NP*NH];
__device__ float g_K1T[NP*D];
__device__ float g_V1T[NP*D];
__device__ float g_K2T[NP*D];
__device__ float g_V2T[NP*D];
__device__ float g_T1[NP*NP*NH];
__device__ float g_T2[NP*NP*NH];
__device__ float g_biasC[NPAD];
// attention-output bf16 hi/lo images: [512 blocks][128 rows x 128 k swizzled = 32KB]
__device__ uint4 g_AttnHi[(size_t)512*2048];
__device__ uint4 g_AttnLo[(size_t)512*2048];
// weight images (bf16 hi/lo, swizzled, B-operand layout: row=output col, col=k)
__device__ uint4 g_WOimgHi[2048];
__device__ uint4 g_WOimgLo[2048];
__device__ uint4 g_W1imgHi[4*2048];
__device__ uint4 g_W1imgLo[4*2048];
__device__ uint4 g_WimgHi[5*2560];   // Wcat slabs (160 rows)
__device__ uint4 g_WimgLo[5*2560];

// image addressing: rows of 256B (128 bf16), 16B chunks XOR-swizzled by (row&7)
__device__ __forceinline__ unsigned img_off_elem(int r, int k){
    return (unsigned)r*256u + ((((unsigned)k>>3)^((unsigned)r&7u))*16u) + ((unsigned)k&7u)*2u;
}

// split f32 pair -> bf16 hi/lo, 4-byte write at (r, col even)
__device__ __forceinline__ void wpair(char* hiB, char* loB, int r, int col, float a, float b){
    __nv_bfloat16 h0=__float2bfloat16(a), h1=__float2bfloat16(b);
    float r0=a-__bfloat162float(h0), r1=b-__bfloat162float(h1);
    __nv_bfloat16 l0=__float2bfloat16(r0), l1=__float2bfloat16(r1);
    unsigned off = (unsigned)r*256u + ((((unsigned)col>>3)^((unsigned)r&7u))*16u) + ((unsigned)col&7u)*2u;
    unsigned hv = (unsigned)*(unsigned short*)&h0 | ((unsigned)*(unsigned short*)&h1<<16);
    unsigned lv = (unsigned)*(unsigned short*)&l0 | ((unsigned)*(unsigned short*)&l1<<16);
    *(unsigned*)(hiB+off)=hv;
    *(unsigned*)(loB+off)=lv;
}

// ---------------- precompute per-p and per-token tables ----------------
__global__ void k_precompute(
    const float* __restrict__ emb, const float* __restrict__ pos,
    const float* __restrict__ W_mem, const float* __restrict__ b_mem,
    const float* __restrict__ W_sur, const float* __restrict__ b_sur,
    const float* __restrict__ W_m2r, const float* __restrict__ b_m2r,
    const float* __restrict__ W_Q, const float* __restrict__ W_K,
    const float* __restrict__ W_V)
{
    int p = blockIdx.x;
    int d = threadIdx.x; // 128 threads
    __shared__ float x0f[D], zz[DMEM], diffs[D], zu[DMEM], memv[D];
    __shared__ float x0full[D], x3full[D];
    __shared__ float sq[D], sk0[D], sk3[D], skm[D], e1v[D], e2v[D];

    x0f[d] = emb[p*D+d] + pos[d];
    __syncthreads();
    if (d < DMEM){
        float acc = b_mem[d];
        for (int e=0;e<D;e++) acc += x0f[e]*W_mem[e*DMEM+d];
        zz[d] = acc/(1.f+expf(-acc));        // silu
    }
    __syncthreads();
    {
        float pr = b_sur[d];
        for (int j=0;j<DMEM;j++) pr += zz[j]*W_sur[j*D+d];
        diffs[d] = x0f[d] - pr;
    }
    __syncthreads();
    if (d < DMEM){
        float acc = 0.f;
        for (int e=0;e<D;e++) acc += diffs[e]*W_mem[e*DMEM+d];
        zu[d] = zz[d] + acc/(1.f+expf(-acc));
    }
    __syncthreads();
    {
        float mm = b_m2r[d];
        for (int j=0;j<DMEM;j++) mm += zu[j]*W_m2r[j*D+d];
        memv[d]  = mm;
        x0full[d] = x0f[d] + mm;
        x3full[d] = emb[EQTOK*D+d] + pos[3*D+d] + mm;
        e1v[d] = emb[p*D+d] + pos[D+d];
        e2v[d] = emb[p*D+d] + pos[2*D+d];
    }
    __syncthreads();

    int h = d>>5;
    const float* Wq = W_Q + h*D*DH + (d&31);
    const float* Wk = W_K + h*D*DH + (d&31);
    const float* Wv = W_V + h*D*DH + (d&31);
    float q=0,k0=0,k3=0,km=0,v0=0,v3=0,vm=0,k1=0,v1=0,k2=0,v2=0;
    for (int e=0;e<D;e++){
        float wq=Wq[e*DH], wk=Wk[e*DH], wv=Wv[e*DH];
        q  += x3full[e]*wq;
        k0 += x0full[e]*wk; k3 += x3full[e]*wk; km += memv[e]*wk;
        v0 += x0full[e]*wv; v3 += x3full[e]*wv; vm += memv[e]*wv;
        k1 += e1v[e]*wk;    v1 += e1v[e]*wv;
        k2 += e2v[e]*wk;    v2 += e2v[e]*wv;
    }
    q *= 0.17677669529663687f;  // 1/sqrt(32)
    g_Q3[p*D+d]=q;  g_X3F[p*D+d]=x3full[d];
    g_V0[p*D+d]=v0; g_V3[p*D+d]=v3; g_VM[p*D+d]=vm;
    g_K1T[p*D+d]=k1; g_V1T[p*D+d]=v1; g_K2T[p*D+d]=k2; g_V2T[p*D+d]=v2;
    sq[d]=q; sk0[d]=k0; sk3[d]=k3; skm[d]=km;
    __syncthreads();
    if (d < 3*NH){
        int hh = d & 3, which = d >> 2;
        const float* kk = (which==0) ? sk0 : (which==1 ? sk3 : skm);
        float acc=0.f;
        for (int t=0;t<DH;t++) acc += sq[hh*DH+t]*kk[hh*DH+t];
        float* dst = (which==0) ? g_S0 : (which==1 ? g_S3 : g_SM);
        dst[p*NH+hh] = acc;
    }
}

// ---------------- bilinear score tables T1/T2 ----------------
__global__ void k_ttab(){
    int p = blockIdx.x;
    __shared__ float q[D];
    int t = threadIdx.x;
    q[t] = g_Q3[p*D+t];
    __syncthreads();
    for (int a=t; a<NP; a+=128){
        for (int h=0;h<NH;h++){
            float s1=0.f, s2=0.f;
            for (int k=0;k<DH;k++){
                float qv = q[h*DH+k];
                s1 += qv*g_K1T[a*D+h*DH+k];
                s2 += qv*g_K2T[a*D+h*DH+k];
            }
            g_T1[(p*NP+a)*NH+h] = s1;
            g_T2[(p*NP+a)*NH+h] = s2;
        }
    }
}

// ---------------- fold W2@Wun, bias, build WcatT images ----------------
__global__ void k_wcat(const float* __restrict__ W_un, const float* __restrict__ b_un,
                       const float* __restrict__ W2,   const float* __restrict__ b2){
    int r = blockIdx.x;      // 0..639  (K dim of Wcat)
    int n = threadIdx.x;     // 0..159  (output col)
    float val = 0.f;
    if (n < NOUT){
        if (r < D) val = W_un[r*NOUT+n];
        else {
            int j = r - D;
            float acc = 0.f;
            for (int dd=0;dd<D;dd++) acc += W2[j*D+dd]*W_un[dd*NOUT+n];
            val = acc;
        }
    }
    int slab = r >> 7, kk = r & 127;
    __nv_bfloat16 h = __float2bfloat16(val);
    float res = val - __bfloat162float(h);
    __nv_bfloat16 l = __float2bfloat16(res);
    unsigned off = img_off_elem(n, kk);
    *(unsigned short*)((char*)g_WimgHi + (size_t)slab*40960 + off) = *(unsigned short*)&h;
    *(unsigned short*)((char*)g_WimgLo + (size_t)slab*40960 + off) = *(unsigned short*)&l;
    if (r == 0){
        float bc = 0.f;
        if (n < NOUT){
            bc = b_un[n];
            for (int dd=0;dd<D;dd++) bc += b2[dd]*W_un[dd*NOUT+n];
        }
        g_biasC[n] = bc;
    }
}

// ---------------- build W_O / W1 bf16 hi/lo images ----------------
__global__ void k_wimg(const float* __restrict__ WO, const float* __restrict__ W1){
    int bx = blockIdx.x;     // 0..639
    int k  = threadIdx.x;    // 0..127
    float val; char* hiB; char* loB; int rowc;
    if (bx < 128){
        rowc = bx;
        val = WO[k*D + rowc];
        hiB = (char*)g_WOimgHi; loB = (char*)g_WOimgLo;
    } else {
        int idx = bx - 128;
        int ch = idx >> 7, j = idx & 127;
        rowc = j;
        val = W1[k*DMLP + ch*128 + j];
        hiB = (char*)g_W1imgHi + (size_t)ch*32768;
        loB = (char*)g_W1imgLo + (size_t)ch*32768;
    }
    __nv_bfloat16 h = __float2bfloat16(val);
    float res = val - __bfloat162float(h);
    __nv_bfloat16 l = __float2bfloat16(res);
    unsigned off = img_off_elem(rowc, k);
    *(unsigned short*)(hiB + off) = *(unsigned short*)&h;
    *(unsigned short*)(loB + off) = *(unsigned short*)&l;
}

// ---------------- per-example attention; writes bf16 hi/lo images ----------------
__global__ void k_attn(const int* __restrict__ pv, const int* __restrict__ av,
                       const int* __restrict__ bv){
    int idx  = blockIdx.x*blockDim.x + threadIdx.x;
    int ex   = idx >> 5;
    int lane = idx & 31;
    int p = pv[ex], a = av[ex], b = bv[ex];
    int h = lane >> 3;
    float smv = g_SM[p*NH+h];
    float s0  = g_S0[p*NH+h];
    float s3  = g_S3[p*NH+h];
    float s1  = g_T1[(p*NP+a)*NH+h] + smv;
    float s2  = g_T2[(p*NP+b)*NH+h] + smv;
    float m  = fmaxf(fmaxf(s0,s1),fmaxf(s2,s3));
    float e0=expf(s0-m), e1=expf(s1-m), e2=expf(s2-m), e3=expf(s3-m);
    float inv = 1.f/(e0+e1+e2+e3);
    float w0=e0*inv, w1=e1*inv, w2=e2*inv, w3=e3*inv, w12=w1+w2;
    int d0 = lane*4;
    float4 V0 = *(const float4*)&g_V0 [p*D+d0];
    float4 V3 = *(const float4*)&g_V3 [p*D+d0];
    float4 VM = *(const float4*)&g_VM [p*D+d0];
    float4 Va = *(const float4*)&g_V1T[a*D+d0];
    float4 Vb = *(const float4*)&g_V2T[b*D+d0];
    float o[4];
    o[0] = w0*V0.x + w3*V3.x + w12*VM.x + w1*Va.x + w2*Vb.x;
    o[1] = w0*V0.y + w3*V3.y + w12*VM.y + w1*Va.y + w2*Vb.y;
    o[2] = w0*V0.z + w3*V3.z + w12*VM.z + w1*Va.z + w2*Vb.z;
    o[3] = w0*V0.w + w3*V3.w + w12*VM.w + w1*Va.w + w2*Vb.w;
    // split and write 8B hi + 8B lo into block image
    union { unsigned short s[4]; uint2 q; } H, L;
    #pragma unroll
    for (int j=0;j<4;j++){
        __nv_bfloat16 hh = __float2bfloat16(o[j]);
        float res = o[j] - __bfloat162float(hh);
        __nv_bfloat16 ll = __float2bfloat16(res);
        H.s[j] = *(unsigned short*)&hh;
        L.s[j] = *(unsigned short*)&ll;
    }
    int blkimg = ex >> 7, r = ex & 127;
    unsigned off = (unsigned)r*256u + ((((unsigned)d0>>3)^((unsigned)r&7u))*16u) + ((unsigned)d0&7u)*2u;
    *(uint2*)((char*)g_AttnHi + (size_t)blkimg*32768 + off) = H.q;
    *(uint2*)((char*)g_AttnLo + (size_t)blkimg*32768 + off) = L.q;
}

// ---------------- fragment-load + MMA pass over one 128-K image pair ----------------
template<int NT>
__device__ __forceinline__ void mma_pass(float (&acc)[2][NT][4], const char* Aimg, const char* Bimg,
                                         int rowbase, int colbase, int lr, int lq){
    #pragma unroll
    for (int ks=0; ks<8; ks++){
        unsigned ch0 = (unsigned)ks*2u, ch1 = ch0+1u;
        uint32_t afr[2][4];
        #pragma unroll
        for (int mt=0; mt<2; mt++){
            int r = rowbase + mt*16 + lr;
            unsigned base = (unsigned)r*256u + (unsigned)lq*4u;
            unsigned o0 = base + ((ch0^((unsigned)r&7u))*16u);
            unsigned o1 = base + ((ch1^((unsigned)r&7u))*16u);
            afr[mt][0] = *(const uint32_t*)(Aimg+o0);
            afr[mt][1] = *(const uint32_t*)(Aimg+o0+2048);
            afr[mt][2] = *(const uint32_t*)(Aimg+o1);
            afr[mt][3] = *(const uint32_t*)(Aimg+o1+2048);
        }
        uint32_t bfr[NT][2];
        #pragma unroll
        for (int nt=0; nt<NT; nt++){
            int n = colbase + nt*8 + lr;
            unsigned base = (unsigned)n*256u + (unsigned)lq*4u;
            bfr[nt][0] = *(const uint32_t*)(Bimg + base + ((ch0^((unsigned)n&7u))*16u));
            bfr[nt][1] = *(const uint32_t*)(Bimg + base + ((ch1^((unsigned)n&7u))*16u));
        }
        #pragma unroll
        for (int mt=0; mt<2; mt++){
            #pragma unroll
            for (int nt=0; nt<NT; nt++) mma16816(acc[mt][nt], afr[mt], bfr[nt]);
        }
    }
}

template<int NT>
__device__ __forceinline__ void mma3(float (&acc)[2][NT][4],
                                     const char* Ahi, const char* Alo,
                                     const char* Bhi, const char* Blo,
                                     int rowbase, int colbase, int lr, int lq){
    mma_pass<NT>(acc, Ahi, Bhi, rowbase, colbase, lr, lq);
    mma_pass<NT>(acc, Alo, Bhi, rowbase, colbase, lr, lq);
    mma_pass<NT>(acc, Ahi, Blo, rowbase, colbase, lr, lq);
}

// ---------------- fused GEMM chain: attn@WO +res -> x3 ; x3@W1 relu -> H ; [x3;H]@Wcat -> logits
#define OFF_X3 65536
#define OFF_W  131072
#define WLO    40960
#define FU_SMEM (131072 + 81920)

__global__ void __launch_bounds__(256)
k_fused(const int* __restrict__ pv, const float* __restrict__ bias1, float* __restrict__ out){
    extern __shared__ char sm[];
    char* B1 = sm;               // 64KB: attn images, later H-chunk images
    char* X3 = sm + OFF_X3;      // 64KB: x3 images
    char* WB = sm + OFF_W;       // 80KB: weight images (hi at 0, lo at +WLO)
    __shared__ int ps[128];
    __shared__ float sb1[128];
    __shared__ float sbc[NPAD];

    int tid = threadIdx.x, wid = tid>>5, lane = tid&31;
    int blk = blockIdx.x;
    int R0  = blk*128;
    int wm = wid & 3, wn = wid >> 2;
    int lr = lane >> 2, lq = lane & 3;
    int rowbase = wm*32;

    if (tid < 128) ps[tid] = pv[R0+tid];
    if (tid < NPAD) sbc[tid] = g_biasC[tid];
    {
        const uint4* sH = g_AttnHi + (size_t)blk*2048;
        const uint4* sL = g_AttnLo + (size_t)blk*2048;
        uint4* dH = (uint4*)B1; uint4* dL = (uint4*)(B1+32768);
        for (int i=tid;i<2048;i+=256){ dH[i]=sH[i]; dL[i]=sL[i]; }
        uint4* wH = (uint4*)WB; uint4* wL = (uint4*)(WB+WLO);
        for (int i=tid;i<2048;i+=256){ wH[i]=g_WOimgHi[i]; wL[i]=g_WOimgLo[i]; }
    }
    __syncthreads();

    // ---- stage A: P = attn @ WO ----
    float accA[2][8][4];
    #pragma unroll
    for (int mt=0;mt<2;mt++){
        #pragma unroll
        for (int nt=0;nt<8;nt++){
            #pragma unroll
            for (int q=0;q<4;q++) accA[mt][nt][q]=0.f;
        }
    }
    mma3<8>(accA, B1, B1+32768, WB, WB+WLO, rowbase, wn*64, lr, lq);

    // ---- x3 = P + X3F[p]; write x3 images ----
    #pragma unroll
    for (int mt=0;mt<2;mt++){
        int r = rowbase + mt*16 + lr;
        #pragma unroll
        for (int nt=0;nt<8;nt++){
            int col = wn*64 + nt*8 + lq*2;
            float v00 = accA[mt][nt][0] + g_X3F[ps[r]*D+col];
            float v01 = accA[mt][nt][1] + g_X3F[ps[r]*D+col+1];
            float v10 = accA[mt][nt][2] + g_X3F[ps[r+8]*D+col];
            float v11 = accA[mt][nt][3] + g_X3F[ps[r+8]*D+col+1];
            wpair(X3, X3+32768, r,   col, v00, v01);
            wpair(X3, X3+32768, r+8, col, v10, v11);
        }
    }
    __syncthreads();

    // ---- logits accumulators ----
    float accL[2][10][4];
    #pragma unroll
    for (int mt=0;mt<2;mt++){
        #pragma unroll
        for (int nt=0;nt<10;nt++){
            #pragma unroll
            for (int q=0;q<4;q++) accL[mt][nt][q]=0.f;
        }
    }

    // slab 0: x3 @ Wcat0
    {
        uint4* wH = (uint4*)WB; uint4* wL = (uint4*)(WB+WLO);
        const uint4* sH = g_WimgHi; const uint4* sL = g_WimgLo;
        for (int i=tid;i<2560;i+=256){ wH[i]=sH[i]; wL[i]=sL[i]; }
    }
    __syncthreads();
    mma3<10>(accL, X3, X3+32768, WB, WB+WLO, rowbase, wn*80, lr, lq);

    // ---- chunks: H = relu(x3@W1ch + b1); logits += H @ Wcat[ch+1] ----
    for (int ch=0; ch<4; ch++){
        __syncthreads();
        {
            uint4* wH = (uint4*)WB; uint4* wL = (uint4*)(WB+WLO);
            const uint4* sH = g_W1imgHi + (size_t)ch*2048;
            const uint4* sL = g_W1imgLo + (size_t)ch*2048;
            for (int i=tid;i<2048;i+=256){ wH[i]=sH[i]; wL[i]=sL[i]; }
        }
        if (tid < 128) sb1[tid] = bias1[ch*128+tid];
        __syncthreads();

        float accH[2][8][4];
        #pragma unroll
        for (int mt=0;mt<2;mt++){
            #pragma unroll
            for (int nt=0;nt<8;nt++){
                #pragma unroll
                for (int q=0;q<4;q++) accH[mt][nt][q]=0.f;
            }
        }
        mma3<8>(accH, X3, X3+32768, WB, WB+WLO, rowbase, wn*64, lr, lq);

        // H epilogue -> B1 images
        #pragma unroll
        for (int mt=0;mt<2;mt++){
            int r = rowbase + mt*16 + lr;
            #pragma unroll
            for (int nt=0;nt<8;nt++){
                int col = wn*64 + nt*8 + lq*2;
                float b0 = sb1[col], b1v = sb1[col+1];
                float v00 = fmaxf(accH[mt][nt][0] + b0,  0.f);
                float v01 = fmaxf(accH[mt][nt][1] + b1v, 0.f);
                float v10 = fmaxf(accH[mt][nt][2] + b0,  0.f);
                float v11 = fmaxf(accH[mt][nt][3] + b1v, 0.f);
                wpair(B1, B1+32768, r,   col, v00, v01);
                wpair(B1, B1+32768, r+8, col, v10, v11);
            }
        }
        __syncthreads();
        {
            uint4* wH = (uint4*)WB; uint4* wL = (uint4*)(WB+WLO);
            const uint4* sH = g_WimgHi + (size_t)(ch+1)*2560;
            const uint4* sL = g_WimgLo + (size_t)(ch+1)*2560;
            for (int i=tid;i<2560;i+=256){ wH[i]=sH[i]; wL[i]=sL[i]; }
        }
        __syncthreads();
        mma3<10>(accL, B1, B1+32768, WB, WB+WLO, rowbase, wn*80, lr, lq);
    }

    // ---- logits epilogue ----
    #pragma unroll
    for (int mt=0;mt<2;mt++){
        int row = R0 + rowbase + mt*16 + lr;
        #pragma unroll
        for (int nt=0;nt<10;nt++){
            int col = wn*80 + nt*8 + lq*2;
            if (col < NOUT){
                out[row*NOUT+col]       = accL[mt][nt][0] + sbc[col];
                out[(row+8)*NOUT+col]   = accL[mt][nt][2] + sbc[col];
            }
            if (col+1 < NOUT){
                out[row*NOUT+col+1]     = accL[mt][nt][1] + sbc[col+1];
                out[(row+8)*NOUT+col+1] = accL[mt][nt][3] + sbc[col+1];
            }
        }
    }
}

// ---------------- launch ----------------
extern "C" void kernel_launch(void* const* d_in, const int* in_sizes, int n_in,
                              void* d_out, int out_size){
    const int*   pv    = (const int*)  d_in[0];
    const int*   av    = (const int*)  d_in[1];
    const int*   bvv   = (const int*)  d_in[2];
    const float* emb   = (const float*)d_in[3];
    const float* pos   = (const float*)d_in[4];
    const float* W_mem = (const float*)d_in[5];
    const float* b_mem = (const float*)d_in[6];
    const float* W_sur = (const float*)d_in[7];
    const float* b_sur = (const float*)d_in[8];
    const float* W_m2r = (const float*)d_in[9];
    const float* b_m2r = (const float*)d_in[10];
    const float* W_Q   = (const float*)d_in[11];
    const float* W_K   = (const float*)d_in[12];
    const float* W_V   = (const float*)d_in[13];
    const float* W_O   = (const float*)d_in[14];
    const float* W1    = (const float*)d_in[15];
    const float* bias1 = (const float*)d_in[16];
    const float* W2    = (const float*)d_in[17];
    const float* b2    = (const float*)d_in[18];
    const float* W_un  = (const float*)d_in[19];
    const float* b_un  = (const float*)d_in[20];
    float* out = (float*)d_out;

    k_precompute<<<NP,128>>>(emb,pos,W_mem,b_mem,W_sur,b_sur,W_m2r,b_m2r,W_Q,W_K,W_V);
    k_ttab<<<NP,128>>>();
    k_wcat<<<D+DMLP,NPAD>>>(W_un,b_un,W2,b2);
    k_wimg<<<D+DMLP,128>>>(W_O,W1);
    k_attn<<<BB/8,256>>>(pv,av,bvv);

    cudaFuncSetAttribute(k_fused, cudaFuncAttributeMaxDynamicSharedMemorySize, FU_SMEM);
    k_fused<<<BB/D,256,FU_SMEM>>>(pv,bias1,out);
}